// round 1
// baseline (speedup 1.0000x reference)
#include <cuda_runtime.h>
#include <cuda_bf16.h>
#include <math.h>

// Problem constants
#define HH 128
#define WW 128
#define HW (HH * WW)          // 16384
#define BATCH 4
#define GRP 8
#define CPG 8
#define NTAP 9

// Scratch (device globals — no allocation allowed)
__device__ float g_target[BATCH * 64 * HW];   // 16 MB
__device__ float g_y1[BATCH * 64 * HW];       // 16 MB
__device__ float g_w1t[128 * 9 * 64];         // w1 transposed [c][k][oc]
__device__ float g_w2t[64 * 9 * 64];          // w2 transposed [c][k][oc]

// ---------------------------------------------------------------------------
// Weight transpose: w[oc][cin][9] -> wt[cin][9][oc]  (coalesced staging later)
// ---------------------------------------------------------------------------
__global__ void prep_weights(const float* __restrict__ w1,
                             const float* __restrict__ w2,
                             float* __restrict__ w1t,
                             float* __restrict__ w2t) {
    int idx = blockIdx.x * blockDim.x + threadIdx.x;
    if (idx < 64 * 128 * 9) {
        int oc = idx / (128 * 9);
        int c  = (idx / 9) % 128;
        int k  = idx % 9;
        w1t[(c * 9 + k) * 64 + oc] = w1[idx];
    }
    if (idx < 64 * 64 * 9) {
        int oc = idx / (64 * 9);
        int c  = (idx / 9) % 64;
        int k  = idx % 9;
        w2t[(c * 9 + k) * 64 + oc] = w2[idx];
    }
}

// ---------------------------------------------------------------------------
// Deformable group kernel.
// grid: (64 tiles of 16x16, G=8, B=4), block: 256 threads (16x16 pixels)
// Each thread: 1 pixel, 1 group -> computes 18 offsets + 9 masks via 3x3 conv
// over the motion slice f, then 9-tap modulated bilinear sampling of anchor
// slice x, contracted with cw into 8 output channels.
// ---------------------------------------------------------------------------
__global__ __launch_bounds__(256) void deform_kernel(
    const float* __restrict__ o,       // (B,64,H,W) motion source
    const float* __restrict__ anchor,  // (B,64,H,W) sampled features
    const float* __restrict__ pw,      // (G,18,8,3,3)
    const float* __restrict__ pb,      // (G,18)
    const float* __restrict__ mw,      // (G,9,8,3,3)
    const float* __restrict__ mb,      // (G,9)
    const float* __restrict__ cw,      // (G,8,8,3,3)
    float* __restrict__ target)        // (B,64,H,W)
{
    const int b = blockIdx.z;
    const int g = blockIdx.y;
    const int tile = blockIdx.x;                 // 0..63
    const int ty0 = (tile >> 3) * 16;
    const int tx0 = (tile & 7) * 16;
    const int tid = threadIdx.x;
    const int lx = tid & 15;
    const int ly = tid >> 4;
    const int i = ty0 + ly;                      // output row
    const int j = tx0 + lx;                      // output col

    __shared__ float ftile[8][18][18];           // f slice tile with halo
    __shared__ float wall[8][3][3][28];          // 27 conv outputs, padded to 28
    __shared__ float cwg[9][8][8];               // [n][c][oc]
    __shared__ float bias27[27];

    // ---- stage f tile (8 channels, 18x18 with zero halo) ----
    const float* fbase = o + (size_t)(b * 64 + g * 8) * HW;
    for (int idx = tid; idx < 8 * 18 * 18; idx += 256) {
        int c   = idx / 324;
        int r   = (idx % 324) / 18;
        int col = idx % 18;
        int gi = ty0 + r - 1, gj = tx0 + col - 1;
        float v = 0.f;
        if (gi >= 0 && gi < HH && gj >= 0 && gj < WW)
            v = fbase[c * HW + gi * WW + gj];
        ftile[c][r][col] = v;
    }

    // ---- stage weights ----
    const float* pwg = pw + g * 18 * 8 * 9;
    const float* mwg = mw + g * 9 * 8 * 9;
    for (int idx = tid; idx < 8 * 9 * 27; idx += 256) {
        int o27  = idx % 27;
        int rest = idx / 27;           // c*9 + k
        int c = rest / 9;
        int k = rest % 9;
        float v = (o27 < 18) ? pwg[(o27 * 8 + c) * 9 + k]
                             : mwg[((o27 - 18) * 8 + c) * 9 + k];
        wall[c][k / 3][k % 3][o27] = v;
    }
    for (int idx = tid; idx < 72; idx += 256) {          // zero pad lane 27
        int c = idx / 9, k = idx % 9;
        wall[c][k / 3][k % 3][27] = 0.f;
    }
    for (int idx = tid; idx < 8 * 8 * 9; idx += 256) {
        int oc = idx / 72;
        int c  = (idx / 9) % 8;
        int n  = idx % 9;
        cwg[n][c][oc] = cw[((g * 8 + oc) * 8 + c) * 9 + n];
    }
    if (tid < 27)
        bias27[tid] = (tid < 18) ? pb[g * 18 + tid] : mb[g * 9 + tid - 18];
    __syncthreads();

    // ---- offset + mask conv: 27 outputs in registers ----
    float accO[28];
#pragma unroll
    for (int k = 0; k < 27; k++) accO[k] = bias27[k];
    accO[27] = 0.f;

#pragma unroll
    for (int c = 0; c < 8; c++) {
#pragma unroll
        for (int kr = 0; kr < 3; kr++) {
#pragma unroll
            for (int kc = 0; kc < 3; kc++) {
                float fv = ftile[c][ly + kr][lx + kc];
                const float4* wv4 = (const float4*)wall[c][kr][kc];
#pragma unroll
                for (int q = 0; q < 7; q++) {
                    float4 wv = wv4[q];
                    accO[q * 4 + 0] += fv * wv.x;
                    accO[q * 4 + 1] += fv * wv.y;
                    accO[q * 4 + 2] += fv * wv.z;
                    accO[q * 4 + 3] += fv * wv.w;
                }
            }
        }
    }

    // ---- modulated bilinear sampling + contraction with cw ----
    float acc[8];
#pragma unroll
    for (int oc = 0; oc < 8; oc++) acc[oc] = 0.f;

    const float* xbase = anchor + (size_t)(b * 64 + g * 8) * HW;

#pragma unroll
    for (int n = 0; n < 9; n++) {
        float offx = accO[n];
        float offy = accO[9 + n];
        float mval = 1.f / (1.f + expf(-accO[18 + n]));

        // base grid starts at 1; pn_x = n/3-1, pn_y = n%3-1
        float px = (float)(i + n / 3) + offx;
        float py = (float)(j + n % 3) + offy;

        float fx = floorf(px);
        float fy = floorf(py);
        float pxc = fminf(fmaxf(px, 0.f), 127.f);
        float pyc = fminf(fmaxf(py, 0.f), 127.f);

        float qxlt = fminf(fmaxf(fx, 0.f), 127.f);
        float qxrb = fminf(fmaxf(fx + 1.f, 0.f), 127.f);
        float qylt = fminf(fmaxf(fy, 0.f), 127.f);
        float qyrb = fminf(fmaxf(fy + 1.f, 0.f), 127.f);

        float glt = (1.f + (qxlt - pxc)) * (1.f + (qylt - pyc)) * mval;
        float grb = (1.f - (qxrb - pxc)) * (1.f - (qyrb - pyc)) * mval;
        float glb = (1.f + (qxlt - pxc)) * (1.f - (qyrb - pyc)) * mval;
        float grt = (1.f - (qxrb - pxc)) * (1.f + (qylt - pyc)) * mval;

        int xlt = (int)qxlt, xrb = (int)qxrb;
        int ylt = (int)qylt, yrb = (int)qyrb;
        int i_lt = xlt * WW + ylt;
        int i_rb = xrb * WW + yrb;
        int i_lb = xlt * WW + yrb;
        int i_rt = xrb * WW + ylt;

#pragma unroll
        for (int c = 0; c < 8; c++) {
            const float* xc = xbase + c * HW;
            float val = glt * __ldg(xc + i_lt) + grb * __ldg(xc + i_rb)
                      + glb * __ldg(xc + i_lb) + grt * __ldg(xc + i_rt);
            const float4* cw4 = (const float4*)cwg[n][c];
            float4 c0 = cw4[0], c1 = cw4[1];
            acc[0] += val * c0.x; acc[1] += val * c0.y;
            acc[2] += val * c0.z; acc[3] += val * c0.w;
            acc[4] += val * c1.x; acc[5] += val * c1.y;
            acc[6] += val * c1.z; acc[7] += val * c1.w;
        }
    }

    float* tb = target + (size_t)(b * 64 + g * 8) * HW + i * WW + j;
#pragma unroll
    for (int oc = 0; oc < 8; oc++) tb[oc * HW] = acc[oc];
}

// ---------------------------------------------------------------------------
// Generic 3x3 conv, pad=1, 64 output channels, optional residual add.
// Input channels come from src0 (c<64) and src1 (c>=64, may be null).
// Weights pre-transposed to wt[c][k][64]. One thread = one pixel, 64 acc regs.
// grid: (64 tiles, 1, B), block: 256
// ---------------------------------------------------------------------------
template <int CIN>
__global__ __launch_bounds__(256) void conv3x3_kernel(
    const float* __restrict__ src0,
    const float* __restrict__ src1,
    const float* __restrict__ wt,     // [CIN][9][64]
    const float* __restrict__ bias,   // [64]
    const float* __restrict__ resid,  // optional (B,64,H,W) or null
    float* __restrict__ out)          // (B,64,H,W)
{
    const int b = blockIdx.z;
    const int tile = blockIdx.x;
    const int ty0 = (tile >> 3) * 16;
    const int tx0 = (tile & 7) * 16;
    const int tid = threadIdx.x;
    const int lx = tid & 15;
    const int ly = tid >> 4;
    const int i = ty0 + ly;
    const int j = tx0 + lx;

    __shared__ float tile_s[18][18];
    __shared__ float ws[9][64];

    float acc[64];
#pragma unroll
    for (int oc = 0; oc < 64; oc++) acc[oc] = bias[oc];

    for (int c = 0; c < CIN; c++) {
        const float* sp = (c < 64)
            ? (src0 + (size_t)(b * 64 + c) * HW)
            : (src1 + (size_t)(b * 64 + (c - 64)) * HW);

        __syncthreads();
        // stage input tile with halo
        for (int idx = tid; idx < 324; idx += 256) {
            int r = idx / 18, col = idx % 18;
            int gi = ty0 + r - 1, gj = tx0 + col - 1;
            tile_s[r][col] = (gi >= 0 && gi < HH && gj >= 0 && gj < WW)
                                 ? sp[gi * WW + gj] : 0.f;
        }
        // stage weights for this input channel (contiguous 576 floats)
        {
            const float4* wsrc = (const float4*)(wt + c * 576);
            float4* wdst = (float4*)ws;
            for (int idx = tid; idx < 144; idx += 256) wdst[idx] = wsrc[idx];
        }
        __syncthreads();

#pragma unroll
        for (int kr = 0; kr < 3; kr++) {
#pragma unroll
            for (int kc = 0; kc < 3; kc++) {
                float v = tile_s[ly + kr][lx + kc];
                const float4* wp = (const float4*)ws[kr * 3 + kc];
#pragma unroll
                for (int q = 0; q < 16; q++) {
                    float4 wv = wp[q];
                    acc[q * 4 + 0] += v * wv.x;
                    acc[q * 4 + 1] += v * wv.y;
                    acc[q * 4 + 2] += v * wv.z;
                    acc[q * 4 + 3] += v * wv.w;
                }
            }
        }
    }

    float* ob = out + (size_t)(b * 64) * HW + i * WW + j;
    if (resid != nullptr) {
        const float* rb = resid + (size_t)(b * 64) * HW + i * WW + j;
#pragma unroll
        for (int oc = 0; oc < 64; oc++) ob[oc * HW] = acc[oc] + rb[oc * HW];
    } else {
#pragma unroll
        for (int oc = 0; oc < 64; oc++) ob[oc * HW] = acc[oc];
    }
}

// ---------------------------------------------------------------------------
// Launch
// ---------------------------------------------------------------------------
extern "C" void kernel_launch(void* const* d_in, const int* in_sizes, int n_in,
                              void* d_out, int out_size) {
    const float* o      = (const float*)d_in[0];
    const float* anchor = (const float*)d_in[1];
    const float* pw     = (const float*)d_in[2];
    const float* pb     = (const float*)d_in[3];
    const float* mw     = (const float*)d_in[4];
    const float* mb     = (const float*)d_in[5];
    const float* cw     = (const float*)d_in[6];
    const float* w1     = (const float*)d_in[7];
    const float* b1     = (const float*)d_in[8];
    const float* w2     = (const float*)d_in[9];
    const float* b2     = (const float*)d_in[10];
    float* out = (float*)d_out;

    float *tgt, *y1, *w1t, *w2t;
    cudaGetSymbolAddress((void**)&tgt, g_target);
    cudaGetSymbolAddress((void**)&y1, g_y1);
    cudaGetSymbolAddress((void**)&w1t, g_w1t);
    cudaGetSymbolAddress((void**)&w2t, g_w2t);

    prep_weights<<<288, 256>>>(w1, w2, w1t, w2t);
    deform_kernel<<<dim3(64, GRP, BATCH), 256>>>(o, anchor, pw, pb, mw, mb, cw, tgt);
    conv3x3_kernel<128><<<dim3(64, 1, BATCH), 256>>>(tgt, anchor, w1t, b1, nullptr, y1);
    conv3x3_kernel<64><<<dim3(64, 1, BATCH), 256>>>(y1, nullptr, w2t, b2, tgt, out);
}